// round 3
// baseline (speedup 1.0000x reference)
#include <cuda_runtime.h>

// PixCorr: per-row Pearson correlation, mean over rows.
// preds, targets: [256, 3, 256, 256] fp32, row-major -> each row is a
// contiguous block of D = 196608 floats.
//
// Kernel 1: one CTA per row, single streaming pass computing
//   sz, sb, szz, sbb, szb  (5 running sums), then
//   corr = (szb - sz*sb/D) / (sqrt(szz - sz^2/D)*sqrt(sbb - sb^2/D) + 1e-6)
// Kernel 2: reduce 256 corr values to their mean.

#define NROWS   256
#define D_ELEMS 196608          // 3*256*256
#define NVEC    (D_ELEMS / 4)   // 49152 float4 per row
#define THREADS 1024
#define EPS     1e-6f

__device__ float g_corr[NROWS];

__device__ __forceinline__ float warp_sum(float v) {
    v += __shfl_xor_sync(0xFFFFFFFFu, v, 16);
    v += __shfl_xor_sync(0xFFFFFFFFu, v, 8);
    v += __shfl_xor_sync(0xFFFFFFFFu, v, 4);
    v += __shfl_xor_sync(0xFFFFFFFFu, v, 2);
    v += __shfl_xor_sync(0xFFFFFFFFu, v, 1);
    return v;
}

__global__ __launch_bounds__(THREADS, 1)
void pixcorr_row_kernel(const float* __restrict__ preds,
                        const float* __restrict__ targets) {
    const int row = blockIdx.x;
    const float4* __restrict__ z4 =
        reinterpret_cast<const float4*>(targets + (size_t)row * D_ELEMS);
    const float4* __restrict__ b4 =
        reinterpret_cast<const float4*>(preds + (size_t)row * D_ELEMS);

    float sz = 0.f, sb = 0.f, szz = 0.f, sbb = 0.f, szb = 0.f;

    // NVEC / THREADS = 48 iterations per thread, fully coalesced float4 loads.
    #pragma unroll 4
    for (int i = threadIdx.x; i < NVEC; i += THREADS) {
        float4 zv = z4[i];
        float4 bv = b4[i];
        sz  += (zv.x + zv.y) + (zv.z + zv.w);
        sb  += (bv.x + bv.y) + (bv.z + bv.w);
        szz  = fmaf(zv.x, zv.x, fmaf(zv.y, zv.y, fmaf(zv.z, zv.z, fmaf(zv.w, zv.w, szz))));
        sbb  = fmaf(bv.x, bv.x, fmaf(bv.y, bv.y, fmaf(bv.z, bv.z, fmaf(bv.w, bv.w, sbb))));
        szb  = fmaf(zv.x, bv.x, fmaf(zv.y, bv.y, fmaf(zv.z, bv.z, fmaf(zv.w, bv.w, szb))));
    }

    // Warp-level reduce of 5 partials.
    sz  = warp_sum(sz);
    sb  = warp_sum(sb);
    szz = warp_sum(szz);
    sbb = warp_sum(sbb);
    szb = warp_sum(szb);

    __shared__ float sh[5][THREADS / 32];
    const int lane = threadIdx.x & 31;
    const int wid  = threadIdx.x >> 5;
    if (lane == 0) {
        sh[0][wid] = sz;  sh[1][wid] = sb;
        sh[2][wid] = szz; sh[3][wid] = sbb; sh[4][wid] = szb;
    }
    __syncthreads();

    if (wid == 0) {
        // 32 warps -> 32 entries: exactly one warp's worth.
        float a0 = sh[0][lane];
        float a1 = sh[1][lane];
        float a2 = sh[2][lane];
        float a3 = sh[3][lane];
        float a4 = sh[4][lane];
        a0 = warp_sum(a0);
        a1 = warp_sum(a1);
        a2 = warp_sum(a2);
        a3 = warp_sum(a3);
        a4 = warp_sum(a4);
        if (lane == 0) {
            const float invD = 1.0f / (float)D_ELEMS;
            float cov = a4 - a0 * a1 * invD;           // szb - sz*sb/D
            float vz  = a2 - a0 * a0 * invD;           // szz - sz^2/D
            float vb  = a3 - a1 * a1 * invD;           // sbb - sb^2/D
            vz = fmaxf(vz, 0.f);
            vb = fmaxf(vb, 0.f);
            float denom = sqrtf(vz) * sqrtf(vb) + EPS;
            g_corr[row] = cov / denom;
        }
    }
}

__global__ void pixcorr_mean_kernel(float* __restrict__ out) {
    // 256 threads = 8 warps
    float v = g_corr[threadIdx.x];
    v = warp_sum(v);
    __shared__ float sh[8];
    const int lane = threadIdx.x & 31;
    const int wid  = threadIdx.x >> 5;
    if (lane == 0) sh[wid] = v;
    __syncthreads();
    if (threadIdx.x == 0) {
        float s = 0.f;
        #pragma unroll
        for (int i = 0; i < 8; i++) s += sh[i];
        out[0] = s * (1.0f / (float)NROWS);
    }
}

extern "C" void kernel_launch(void* const* d_in, const int* in_sizes, int n_in,
                              void* d_out, int out_size) {
    const float* preds   = (const float*)d_in[0];
    const float* targets = (const float*)d_in[1];
    float* out = (float*)d_out;

    pixcorr_row_kernel<<<NROWS, THREADS>>>(preds, targets);
    pixcorr_mean_kernel<<<1, NROWS>>>(out);
}